// round 9
// baseline (speedup 1.0000x reference)
#include <cuda_runtime.h>
#include <cuda_bf16.h>
#include <math.h>

// Problem constants (fixed shapes for this problem)
#define NN 32768
#define EE 8192
#define DD 128

// Scratch (static __device__ arrays — allocation-free per harness rules)
__device__ float g_dv[NN];        // node degrees
__device__ float g_de[EE];        // hyperedge degrees
__device__ float g_s[NN];         // dv_inv_sqrt
__device__ float g_dei[EE];       // de_inv
__device__ float g_m1[NN * DD];   // s .* x
__device__ float g_m2[EE * DD];   // H^T @ m1  (then scaled in place by de_inv)
__device__ float g_m4[NN * DD];   // H @ m3

// ---------------------------------------------------------------------------
// helpers
// ---------------------------------------------------------------------------
__device__ __forceinline__ unsigned f2tf(float f) {
    unsigned u;
    asm("cvt.rna.tf32.f32 %0, %1;" : "=r"(u) : "f"(f));
    return u;
}

__device__ __forceinline__ void mma8(float* c, const unsigned* a, const unsigned* b) {
    asm volatile(
        "mma.sync.aligned.m16n8k8.row.col.f32.tf32.tf32.f32 "
        "{%0,%1,%2,%3}, {%4,%5,%6,%7}, {%8,%9}, {%0,%1,%2,%3};\n"
        : "+f"(c[0]), "+f"(c[1]), "+f"(c[2]), "+f"(c[3])
        : "r"(a[0]), "r"(a[1]), "r"(a[2]), "r"(a[3]), "r"(b[0]), "r"(b[1]));
}

// ---------------------------------------------------------------------------
// Kernel 0: zero d_e and m2 (m2 receives split-K atomic adds)
// ---------------------------------------------------------------------------
__global__ void k_zero() {
    int i = blockIdx.x * 256 + threadIdx.x;
    if (i < EE * DD) g_m2[i] = 0.0f;
    if (i < EE) g_de[i] = 0.0f;
}

// ---------------------------------------------------------------------------
// Kernel 1: one pass over H -> row sums (d_v) and col sums (d_e)
// ---------------------------------------------------------------------------
__global__ __launch_bounds__(256) void k_deg(const float* __restrict__ H) {
    __shared__ float rowacc[128];
    const int t = threadIdx.x;
    if (t < 128) rowacc[t] = 0.0f;
    __syncthreads();

    const int r0 = blockIdx.x * 128;
    float col[32];
#pragma unroll
    for (int j = 0; j < 32; j++) col[j] = 0.0f;

    const float4* H4 = reinterpret_cast<const float4*>(H);
    for (int r = 0; r < 128; r++) {
        const float4* row = H4 + (size_t)(r0 + r) * (EE / 4);
        float rs = 0.0f;
#pragma unroll
        for (int j = 0; j < 8; j++) {
            float4 v = row[t * 8 + j];
            col[j * 4 + 0] += v.x;
            col[j * 4 + 1] += v.y;
            col[j * 4 + 2] += v.z;
            col[j * 4 + 3] += v.w;
            rs += (v.x + v.y) + (v.z + v.w);
        }
#pragma unroll
        for (int o = 16; o > 0; o >>= 1) rs += __shfl_xor_sync(0xffffffffu, rs, o);
        if ((t & 31) == 0) atomicAdd(&rowacc[r], rs);
    }
    __syncthreads();
    if (t < 128) g_dv[r0 + t] = rowacc[t];

#pragma unroll
    for (int j = 0; j < 32; j++) atomicAdd(&g_de[t * 32 + j], col[j]);
}

// ---------------------------------------------------------------------------
// Kernel 2: s = 1/(sqrt(d_v)+eps); m1 = s .* x; de_inv = 1/(d_e+eps)
// ---------------------------------------------------------------------------
__global__ void k_prep(const float* __restrict__ x) {
    int i = blockIdx.x * 256 + threadIdx.x;
    if (i < NN * DD) {
        int n = i >> 7;
        float s = 1.0f / (sqrtf(g_dv[n]) + 1e-8f);
        g_m1[i] = s * x[i];
    }
    if (i < NN) g_s[i] = 1.0f / (sqrtf(g_dv[i]) + 1e-8f);
    if (i < EE) g_dei[i] = 1.0f / (g_de[i] + 1e-8f);
}

// ---------------------------------------------------------------------------
// Kernel 4: m2 *= de_inv (row-wise, in place)
// ---------------------------------------------------------------------------
__global__ void k_scale() {
    int i = blockIdx.x * 256 + threadIdx.x;
    if (i < EE * DD) g_m2[i] *= g_dei[i >> 7];
}

// ---------------------------------------------------------------------------
// TF32 GEMM: C(M x 128) = A(M x K) * B(K x 128), fp32 accumulate.
//   AT = false: A[m,k] = A[m*EE + k]   (H used directly, GEMM2)
//   AT = true : A[m,k] = A[k*EE + m]   (H^T access, GEMM1)
//   ATOM: accumulate into C with atomicAdd (split-K), else plain store.
// Block tile 128x128x32, 256 threads = 8 warps (4 m x 2 n), warp tile 32x64.
// ---------------------------------------------------------------------------
template <bool AT, bool ATOM>
__global__ __launch_bounds__(256) void k_gemm(const float* __restrict__ A,
                                              const float* __restrict__ B,
                                              float* __restrict__ C,
                                              int klen) {
    __shared__ unsigned As[32][136];  // [k][m]
    __shared__ unsigned Bs[32][136];  // [k][n]

    const int t = threadIdx.x;
    const int lane = t & 31;
    const int w = t >> 5;
    const int wm = w & 3;   // 0..3  (m: 4 x 32)
    const int wn = w >> 2;  // 0..1  (n: 2 x 64)
    const int m0 = blockIdx.x * 128;
    const int kbase = blockIdx.y * klen;

    float acc[2][8][4];
#pragma unroll
    for (int mt = 0; mt < 2; mt++)
#pragma unroll
        for (int nt = 0; nt < 8; nt++)
#pragma unroll
            for (int i = 0; i < 4; i++) acc[mt][nt][i] = 0.0f;

    float4 ra[4], rb[4];

    auto loadA = [&](int kk) {
#pragma unroll
        for (int i = 0; i < 4; i++) {
            int idx = t + i * 256;
            if (AT) {
                int r = idx >> 5, q = idx & 31;  // r: k-row, q: m/4
                ra[i] = *reinterpret_cast<const float4*>(A + (size_t)(kk + r) * EE + m0 + q * 4);
            } else {
                int r = idx >> 3, q = idx & 7;   // r: m-row, q: k/4
                ra[i] = *reinterpret_cast<const float4*>(A + (size_t)(m0 + r) * EE + kk + q * 4);
            }
        }
    };
    auto loadB = [&](int kk) {
#pragma unroll
        for (int i = 0; i < 4; i++) {
            int idx = t + i * 256;
            int r = idx >> 5, q = idx & 31;
            rb[i] = *reinterpret_cast<const float4*>(B + (size_t)(kk + r) * DD + q * 4);
        }
    };
    auto storeA = [&]() {
#pragma unroll
        for (int i = 0; i < 4; i++) {
            int idx = t + i * 256;
            if (AT) {
                int r = idx >> 5, q = idx & 31;
                uint4 u = make_uint4(f2tf(ra[i].x), f2tf(ra[i].y), f2tf(ra[i].z), f2tf(ra[i].w));
                *reinterpret_cast<uint4*>(&As[r][q * 4]) = u;
            } else {
                int r = idx >> 3, q = idx & 7;
                As[q * 4 + 0][r] = f2tf(ra[i].x);
                As[q * 4 + 1][r] = f2tf(ra[i].y);
                As[q * 4 + 2][r] = f2tf(ra[i].z);
                As[q * 4 + 3][r] = f2tf(ra[i].w);
            }
        }
    };
    auto storeB = [&]() {
#pragma unroll
        for (int i = 0; i < 4; i++) {
            int idx = t + i * 256;
            int r = idx >> 5, q = idx & 31;
            uint4 u = make_uint4(f2tf(rb[i].x), f2tf(rb[i].y), f2tf(rb[i].z), f2tf(rb[i].w));
            *reinterpret_cast<uint4*>(&Bs[r][q * 4]) = u;
        }
    };

    loadA(kbase);
    loadB(kbase);
    storeA();
    storeB();
    __syncthreads();

    const int iters = klen / 32;
    const int gid = lane >> 2, tig = lane & 3;

    for (int kt = 0; kt < iters; kt++) {
        const bool more = (kt + 1) < iters;
        if (more) {
            loadA(kbase + (kt + 1) * 32);
            loadB(kbase + (kt + 1) * 32);
        }
#pragma unroll
        for (int ks = 0; ks < 4; ks++) {
            const int kr = ks * 8;
            unsigned af[2][4];
#pragma unroll
            for (int mt = 0; mt < 2; mt++) {
                int bm = wm * 32 + mt * 16 + gid;
                af[mt][0] = As[kr + tig][bm];
                af[mt][1] = As[kr + tig][bm + 8];
                af[mt][2] = As[kr + tig + 4][bm];
                af[mt][3] = As[kr + tig + 4][bm + 8];
            }
            unsigned bf[8][2];
#pragma unroll
            for (int nt = 0; nt < 8; nt++) {
                int bn = wn * 64 + nt * 8 + gid;
                bf[nt][0] = Bs[kr + tig][bn];
                bf[nt][1] = Bs[kr + tig + 4][bn];
            }
#pragma unroll
            for (int mt = 0; mt < 2; mt++)
#pragma unroll
                for (int nt = 0; nt < 8; nt++) mma8(acc[mt][nt], af[mt], bf[nt]);
        }
        __syncthreads();
        if (more) {
            storeA();
            storeB();
            __syncthreads();
        }
    }

    // Epilogue: c0:(gid,2tig) c1:(gid,2tig+1) c2:(gid+8,2tig) c3:(gid+8,2tig+1)
#pragma unroll
    for (int mt = 0; mt < 2; mt++) {
#pragma unroll
        for (int nt = 0; nt < 8; nt++) {
            int m = m0 + wm * 32 + mt * 16 + gid;
            int n = wn * 64 + nt * 8 + 2 * tig;
            float* p = C + (size_t)m * DD + n;
            if (ATOM) {
                atomicAdd(p, acc[mt][nt][0]);
                atomicAdd(p + 1, acc[mt][nt][1]);
                atomicAdd(p + 8 * DD, acc[mt][nt][2]);
                atomicAdd(p + 8 * DD + 1, acc[mt][nt][3]);
            } else {
                p[0] = acc[mt][nt][0];
                p[1] = acc[mt][nt][1];
                p[8 * DD] = acc[mt][nt][2];
                p[8 * DD + 1] = acc[mt][nt][3];
            }
        }
    }
}

// ---------------------------------------------------------------------------
// Kernel 6: per row n:  v = s[n]*m4[n,:];  h = W@v + b;  relu;  layernorm.
// ---------------------------------------------------------------------------
__global__ __launch_bounds__(256) void k_final(const float* __restrict__ W,
                                               const float* __restrict__ bias,
                                               const float* __restrict__ gamma,
                                               const float* __restrict__ beta,
                                               float* __restrict__ out) {
    __shared__ float vbuf[8][132];
    const int t = threadIdx.x;
    const int lane = t & 31;
    const int w = t >> 5;

    const float4 bb = *reinterpret_cast<const float4*>(bias + 4 * lane);
    const float4 gg = *reinterpret_cast<const float4*>(gamma + 4 * lane);
    const float4 eb = *reinterpret_cast<const float4*>(beta + 4 * lane);
    const float4* W4 = reinterpret_cast<const float4*>(W);

    for (int n = blockIdx.x * 8 + w; n < NN; n += gridDim.x * 8) {
        const float s = g_s[n];
        float4 mv = *reinterpret_cast<const float4*>(g_m4 + (size_t)n * DD + 4 * lane);
        vbuf[w][4 * lane + 0] = s * mv.x;
        vbuf[w][4 * lane + 1] = s * mv.y;
        vbuf[w][4 * lane + 2] = s * mv.z;
        vbuf[w][4 * lane + 3] = s * mv.w;
        __syncwarp();

        float h0 = bb.x, h1 = bb.y, h2 = bb.z, h3 = bb.w;
#pragma unroll 8
        for (int dq = 0; dq < 32; dq++) {
            float4 v4 = *reinterpret_cast<float4*>(&vbuf[w][dq * 4]);
            float4 w0 = W4[(4 * lane + 0) * 32 + dq];
            float4 w1 = W4[(4 * lane + 1) * 32 + dq];
            float4 w2 = W4[(4 * lane + 2) * 32 + dq];
            float4 w3 = W4[(4 * lane + 3) * 32 + dq];
            h0 += w0.x * v4.x + w0.y * v4.y + w0.z * v4.z + w0.w * v4.w;
            h1 += w1.x * v4.x + w1.y * v4.y + w1.z * v4.z + w1.w * v4.w;
            h2 += w2.x * v4.x + w2.y * v4.y + w2.z * v4.z + w2.w * v4.w;
            h3 += w3.x * v4.x + w3.y * v4.y + w3.z * v4.z + w3.w * v4.w;
        }
        h0 = fmaxf(h0, 0.0f);
        h1 = fmaxf(h1, 0.0f);
        h2 = fmaxf(h2, 0.0f);
        h3 = fmaxf(h3, 0.0f);

        float sum = h0 + h1 + h2 + h3;
#pragma unroll
        for (int o = 16; o > 0; o >>= 1) sum += __shfl_xor_sync(0xffffffffu, sum, o);
        const float mu = sum * (1.0f / 128.0f);
        const float d0 = h0 - mu, d1 = h1 - mu, d2 = h2 - mu, d3 = h3 - mu;
        float vs = d0 * d0 + d1 * d1 + d2 * d2 + d3 * d3;
#pragma unroll
        for (int o = 16; o > 0; o >>= 1) vs += __shfl_xor_sync(0xffffffffu, vs, o);
        const float inv = rsqrtf(vs * (1.0f / 128.0f) + 1e-5f);

        float4 o4;
        o4.x = gg.x * d0 * inv + eb.x;
        o4.y = gg.y * d1 * inv + eb.y;
        o4.z = gg.z * d2 * inv + eb.z;
        o4.w = gg.w * d3 * inv + eb.w;
        *reinterpret_cast<float4*>(out + (size_t)n * DD + 4 * lane) = o4;
        __syncwarp();
    }
}

// ---------------------------------------------------------------------------
// Launch.  CRITICAL FIX vs round 7: __device__ symbols must be resolved with
// cudaGetSymbolAddress before being passed as kernel arguments — naming them
// directly in host code passes the host-side shadow (which GB300's ATS happily
// dereferences as zeros, silently dropping the whole conv contribution).
// ---------------------------------------------------------------------------
extern "C" void kernel_launch(void* const* d_in, const int* in_sizes, int n_in,
                              void* d_out, int out_size) {
    const float* x     = (const float*)d_in[0];   // (N, 128)
    const float* H     = (const float*)d_in[1];   // (N, E)
    const float* W     = (const float*)d_in[2];   // (128, 128)
    const float* bias  = (const float*)d_in[3];   // (128,)
    const float* gamma = (const float*)d_in[4];   // (128,)
    const float* beta  = (const float*)d_in[5];   // (128,)
    float* out = (float*)d_out;

    // Resolve true device addresses of scratch symbols (query only — no alloc,
    // no stream node; legal under graph capture).
    float *p_m1 = nullptr, *p_m2 = nullptr, *p_m4 = nullptr;
    cudaGetSymbolAddress((void**)&p_m1, g_m1);
    cudaGetSymbolAddress((void**)&p_m2, g_m2);
    cudaGetSymbolAddress((void**)&p_m4, g_m4);

    // 0. zero d_e + m2 (split-K accumulator)
    k_zero<<<(EE * DD + 255) / 256, 256>>>();
    // 1. degrees (single pass over H)
    k_deg<<<NN / 128, 256>>>(H);
    // 2. s, m1 = s.*x, de_inv
    k_prep<<<(NN * DD) / 256, 256>>>(x);
    // 3. GEMM1: m2 += H^T @ m1   (M=E, K=N, split-K=4, atomic)
    k_gemm<true, true><<<dim3(EE / 128, 4), 256>>>(H, p_m1, p_m2, NN / 4);
    // 4. m3 = de_inv .* m2 (in place)
    k_scale<<<(EE * DD) / 256, 256>>>();
    // 5. GEMM2: m4 = H @ m3      (M=N, K=E)
    k_gemm<false, false><<<dim3(NN / 128, 1), 256>>>(H, p_m2, p_m4, EE);
    // 6. linear + relu + layernorm
    k_final<<<256, 256>>>(W, bias, gamma, beta, out);
}

// round 10
// speedup vs baseline: 1.1719x; 1.1719x over previous
#include <cuda_runtime.h>
#include <cuda_bf16.h>
#include <math.h>

// Problem constants (fixed shapes for this problem)
#define NN 32768
#define EE 8192
#define DD 128

// Scratch (static __device__ arrays — allocation-free per harness rules)
__device__ float g_dv[NN];        // node degrees
__device__ float g_de[EE];        // hyperedge degrees
__device__ float g_s[NN];         // dv_inv_sqrt
__device__ float g_dei[EE];       // de_inv
__device__ float g_m1[NN * DD];   // tf32(s .* x)
__device__ float g_m2[EE * DD];   // H^T @ m1 ; then tf32(de_inv .* m2) in place
__device__ float g_m4[NN * DD];   // H @ m3

// ---------------------------------------------------------------------------
// helpers
// ---------------------------------------------------------------------------
__device__ __forceinline__ unsigned f2tf(float f) {
    unsigned u;
    asm("cvt.rna.tf32.f32 %0, %1;" : "=r"(u) : "f"(f));
    return u;
}

__device__ __forceinline__ void mma8(float* c, const unsigned* a, const unsigned* b) {
    asm volatile(
        "mma.sync.aligned.m16n8k8.row.col.f32.tf32.tf32.f32 "
        "{%0,%1,%2,%3}, {%4,%5,%6,%7}, {%8,%9}, {%0,%1,%2,%3};\n"
        : "+f"(c[0]), "+f"(c[1]), "+f"(c[2]), "+f"(c[3])
        : "r"(a[0]), "r"(a[1]), "r"(a[2]), "r"(a[3]), "r"(b[0]), "r"(b[1]));
}

__device__ __forceinline__ void cp16(unsigned dst, const void* src) {
    asm volatile("cp.async.cg.shared.global [%0], [%1], 16;\n" :: "r"(dst), "l"(src));
}
__device__ __forceinline__ void cp_commit() {
    asm volatile("cp.async.commit_group;\n");
}
__device__ __forceinline__ void cp_wait0() {
    asm volatile("cp.async.wait_group 0;\n" ::: "memory");
}

// ---------------------------------------------------------------------------
// Kernel 0: zero d_e and m2 (m2 receives split-K atomic adds)
// ---------------------------------------------------------------------------
__global__ void k_zero() {
    int i = blockIdx.x * 256 + threadIdx.x;
    if (i < EE * DD) g_m2[i] = 0.0f;
    if (i < EE) g_de[i] = 0.0f;
}

// ---------------------------------------------------------------------------
// Kernel 1: one pass over H -> row sums (d_v) and col sums (d_e)
// ---------------------------------------------------------------------------
__global__ __launch_bounds__(256) void k_deg(const float* __restrict__ H) {
    __shared__ float rowacc[128];
    const int t = threadIdx.x;
    if (t < 128) rowacc[t] = 0.0f;
    __syncthreads();

    const int r0 = blockIdx.x * 128;
    float col[32];
#pragma unroll
    for (int j = 0; j < 32; j++) col[j] = 0.0f;

    const float4* H4 = reinterpret_cast<const float4*>(H);
    for (int r = 0; r < 128; r++) {
        const float4* row = H4 + (size_t)(r0 + r) * (EE / 4);
        float rs = 0.0f;
#pragma unroll
        for (int j = 0; j < 8; j++) {
            float4 v = row[t * 8 + j];
            col[j * 4 + 0] += v.x;
            col[j * 4 + 1] += v.y;
            col[j * 4 + 2] += v.z;
            col[j * 4 + 3] += v.w;
            rs += (v.x + v.y) + (v.z + v.w);
        }
#pragma unroll
        for (int o = 16; o > 0; o >>= 1) rs += __shfl_xor_sync(0xffffffffu, rs, o);
        if ((t & 31) == 0) atomicAdd(&rowacc[r], rs);
    }
    __syncthreads();
    if (t < 128) g_dv[r0 + t] = rowacc[t];

#pragma unroll
    for (int j = 0; j < 32; j++) atomicAdd(&g_de[t * 32 + j], col[j]);
}

// ---------------------------------------------------------------------------
// Kernel 2: s = 1/(sqrt(d_v)+eps); m1 = tf32(s .* x); de_inv = 1/(d_e+eps)
// m1 is pre-rounded to tf32 so the GEMM B-path needs no per-fragment cvt.
// ---------------------------------------------------------------------------
__global__ void k_prep(const float* __restrict__ x) {
    int i = blockIdx.x * 256 + threadIdx.x;
    if (i < NN * DD) {
        int n = i >> 7;
        float s = 1.0f / (sqrtf(g_dv[n]) + 1e-8f);
        g_m1[i] = __uint_as_float(f2tf(s * x[i]));
    }
    if (i < NN) g_s[i] = 1.0f / (sqrtf(g_dv[i]) + 1e-8f);
    if (i < EE) g_dei[i] = 1.0f / (g_de[i] + 1e-8f);
}

// ---------------------------------------------------------------------------
// Kernel 4: m3 = tf32(de_inv .* m2) (row-wise, in place; GEMM2's B operand)
// ---------------------------------------------------------------------------
__global__ void k_scale() {
    int i = blockIdx.x * 256 + threadIdx.x;
    if (i < EE * DD) g_m2[i] = __uint_as_float(f2tf(g_m2[i] * g_dei[i >> 7]));
}

// ---------------------------------------------------------------------------
// TF32 GEMM: C(M x 128) = A(M x K) * B(K x 128), fp32 accumulate.
//   AT = false: A[m,k] = A[m*EE + k]   (H used directly, GEMM2)
//   AT = true : A[m,k] = A[k*EE + m]   (H^T access, GEMM1)
//   ATOM: accumulate into C with atomicAdd (split-K), else plain store.
// Block tile 128x128x32, 256 threads = 8 warps (4 m x 2 n), warp tile 32x64.
// cp.async double-buffered mainloop: ONE __syncthreads per K-iter, loads
// overlap mma. B arrives pre-rounded to tf32; A (H) gets cvt.rna at
// fragment-read time. __launch_bounds__(256,2) -> 2 CTAs/SM (occ 25%).
// Smem layouts (per stage):
//   AT:  As[k][136]  (pad 8: frag banks = 8*tig+gid, conflict-free)
//   !AT: As[m][36]   (pad 4: frag banks = 4*gid+tig, conflict-free)
//   Bs[k][136] always.
// ---------------------------------------------------------------------------
template <bool AT, bool ATOM>
__global__ __launch_bounds__(256, 2) void k_gemm(const float* __restrict__ A,
                                                 const float* __restrict__ B,
                                                 float* __restrict__ C,
                                                 int klen) {
    extern __shared__ float smemf[];
    constexpr int ASZ = AT ? 32 * 136 : 128 * 36;
    constexpr int BSZ = 32 * 136;
    constexpr int STG = ASZ + BSZ;

    const int t = threadIdx.x;
    const int lane = t & 31;
    const int w = t >> 5;
    const int wm = w & 3;   // 0..3  (m: 4 x 32)
    const int wn = w >> 2;  // 0..1  (n: 2 x 64)
    const int m0 = blockIdx.x * 128;
    const int kbase = blockIdx.y * klen;

    float* const asbuf[2] = {smemf, smemf + STG};
    float* const bsbuf[2] = {smemf + ASZ, smemf + STG + ASZ};
    const unsigned sA0 = (unsigned)__cvta_generic_to_shared(asbuf[0]);
    const unsigned sA1 = (unsigned)__cvta_generic_to_shared(asbuf[1]);
    const unsigned sB0 = (unsigned)__cvta_generic_to_shared(bsbuf[0]);
    const unsigned sB1 = (unsigned)__cvta_generic_to_shared(bsbuf[1]);

    float acc[2][8][4];
#pragma unroll
    for (int mt = 0; mt < 2; mt++)
#pragma unroll
        for (int nt = 0; nt < 8; nt++)
#pragma unroll
            for (int i = 0; i < 4; i++) acc[mt][nt][i] = 0.0f;

    auto issue = [&](int kt, int buf) {
        const int kk = kbase + kt * 32;
        const unsigned sa = buf ? sA1 : sA0;
        const unsigned sb = buf ? sB1 : sB0;
#pragma unroll
        for (int i = 0; i < 4; i++) {
            int c = t + i * 256;
            if (AT) {
                int r = c >> 5, q = c & 31;  // 32 rows x 32 16B-chunks
                cp16(sa + (unsigned)(r * 136 + q * 4) * 4u,
                     A + (size_t)(kk + r) * EE + m0 + q * 4);
            } else {
                int r = c >> 3, q = c & 7;   // 128 rows x 8 16B-chunks
                cp16(sa + (unsigned)(r * 36 + q * 4) * 4u,
                     A + (size_t)(m0 + r) * EE + kk + q * 4);
            }
        }
#pragma unroll
        for (int i = 0; i < 4; i++) {
            int c = t + i * 256;
            int r = c >> 5, q = c & 31;
            cp16(sb + (unsigned)(r * 136 + q * 4) * 4u,
                 B + (size_t)(kk + r) * DD + q * 4);
        }
        cp_commit();
    };

    issue(0, 0);

    const int iters = klen / 32;
    const int gid = lane >> 2, tig = lane & 3;

    for (int kt = 0; kt < iters; kt++) {
        cp_wait0();
        __syncthreads();  // (a) stage kt visible, (b) stage kt-1 buffer free
        if (kt + 1 < iters) issue(kt + 1, (kt + 1) & 1);

        const float* as = asbuf[kt & 1];
        const float* bs = bsbuf[kt & 1];
#pragma unroll
        for (int ks = 0; ks < 4; ks++) {
            const int kr = ks * 8;
            unsigned af[2][4];
#pragma unroll
            for (int mt = 0; mt < 2; mt++) {
                int bm = wm * 32 + mt * 16 + gid;
                if (AT) {
                    af[mt][0] = f2tf(as[(kr + tig) * 136 + bm]);
                    af[mt][1] = f2tf(as[(kr + tig) * 136 + bm + 8]);
                    af[mt][2] = f2tf(as[(kr + tig + 4) * 136 + bm]);
                    af[mt][3] = f2tf(as[(kr + tig + 4) * 136 + bm + 8]);
                } else {
                    af[mt][0] = f2tf(as[bm * 36 + kr + tig]);
                    af[mt][1] = f2tf(as[(bm + 8) * 36 + kr + tig]);
                    af[mt][2] = f2tf(as[bm * 36 + kr + tig + 4]);
                    af[mt][3] = f2tf(as[(bm + 8) * 36 + kr + tig + 4]);
                }
            }
            unsigned bf[8][2];
#pragma unroll
            for (int nt = 0; nt < 8; nt++) {
                int bn = wn * 64 + nt * 8 + gid;
                bf[nt][0] = __float_as_uint(bs[(kr + tig) * 136 + bn]);
                bf[nt][1] = __float_as_uint(bs[(kr + tig + 4) * 136 + bn]);
            }
#pragma unroll
            for (int mt = 0; mt < 2; mt++)
#pragma unroll
                for (int nt = 0; nt < 8; nt++) mma8(acc[mt][nt], af[mt], bf[nt]);
        }
    }

    // Epilogue: c0:(gid,2tig) c1:(gid,2tig+1) c2:(gid+8,2tig) c3:(gid+8,2tig+1)
#pragma unroll
    for (int mt = 0; mt < 2; mt++) {
#pragma unroll
        for (int nt = 0; nt < 8; nt++) {
            int m = m0 + wm * 32 + mt * 16 + gid;
            int n = wn * 64 + nt * 8 + 2 * tig;
            float* p = C + (size_t)m * DD + n;
            if (ATOM) {
                atomicAdd(p, acc[mt][nt][0]);
                atomicAdd(p + 1, acc[mt][nt][1]);
                atomicAdd(p + 8 * DD, acc[mt][nt][2]);
                atomicAdd(p + 8 * DD + 1, acc[mt][nt][3]);
            } else {
                p[0] = acc[mt][nt][0];
                p[1] = acc[mt][nt][1];
                p[8 * DD] = acc[mt][nt][2];
                p[8 * DD + 1] = acc[mt][nt][3];
            }
        }
    }
}

// ---------------------------------------------------------------------------
// Kernel 6: per row n:  v = s[n]*m4[n,:];  h = W@v + b;  relu;  layernorm.
// ---------------------------------------------------------------------------
__global__ __launch_bounds__(256) void k_final(const float* __restrict__ W,
                                               const float* __restrict__ bias,
                                               const float* __restrict__ gamma,
                                               const float* __restrict__ beta,
                                               float* __restrict__ out) {
    __shared__ float vbuf[8][132];
    const int t = threadIdx.x;
    const int lane = t & 31;
    const int w = t >> 5;

    const float4 bb = *reinterpret_cast<const float4*>(bias + 4 * lane);
    const float4 gg = *reinterpret_cast<const float4*>(gamma + 4 * lane);
    const float4 eb = *reinterpret_cast<const float4*>(beta + 4 * lane);
    const float4* W4 = reinterpret_cast<const float4*>(W);

    for (int n = blockIdx.x * 8 + w; n < NN; n += gridDim.x * 8) {
        const float s = g_s[n];
        float4 mv = *reinterpret_cast<const float4*>(g_m4 + (size_t)n * DD + 4 * lane);
        vbuf[w][4 * lane + 0] = s * mv.x;
        vbuf[w][4 * lane + 1] = s * mv.y;
        vbuf[w][4 * lane + 2] = s * mv.z;
        vbuf[w][4 * lane + 3] = s * mv.w;
        __syncwarp();

        float h0 = bb.x, h1 = bb.y, h2 = bb.z, h3 = bb.w;
#pragma unroll 8
        for (int dq = 0; dq < 32; dq++) {
            float4 v4 = *reinterpret_cast<float4*>(&vbuf[w][dq * 4]);
            float4 w0 = W4[(4 * lane + 0) * 32 + dq];
            float4 w1 = W4[(4 * lane + 1) * 32 + dq];
            float4 w2 = W4[(4 * lane + 2) * 32 + dq];
            float4 w3 = W4[(4 * lane + 3) * 32 + dq];
            h0 += w0.x * v4.x + w0.y * v4.y + w0.z * v4.z + w0.w * v4.w;
            h1 += w1.x * v4.x + w1.y * v4.y + w1.z * v4.z + w1.w * v4.w;
            h2 += w2.x * v4.x + w2.y * v4.y + w2.z * v4.z + w2.w * v4.w;
            h3 += w3.x * v4.x + w3.y * v4.y + w3.z * v4.z + w3.w * v4.w;
        }
        h0 = fmaxf(h0, 0.0f);
        h1 = fmaxf(h1, 0.0f);
        h2 = fmaxf(h2, 0.0f);
        h3 = fmaxf(h3, 0.0f);

        float sum = h0 + h1 + h2 + h3;
#pragma unroll
        for (int o = 16; o > 0; o >>= 1) sum += __shfl_xor_sync(0xffffffffu, sum, o);
        const float mu = sum * (1.0f / 128.0f);
        const float d0 = h0 - mu, d1 = h1 - mu, d2 = h2 - mu, d3 = h3 - mu;
        float vs = d0 * d0 + d1 * d1 + d2 * d2 + d3 * d3;
#pragma unroll
        for (int o = 16; o > 0; o >>= 1) vs += __shfl_xor_sync(0xffffffffu, vs, o);
        const float inv = rsqrtf(vs * (1.0f / 128.0f) + 1e-5f);

        float4 o4;
        o4.x = gg.x * d0 * inv + eb.x;
        o4.y = gg.y * d1 * inv + eb.y;
        o4.z = gg.z * d2 * inv + eb.z;
        o4.w = gg.w * d3 * inv + eb.w;
        *reinterpret_cast<float4*>(out + (size_t)n * DD + 4 * lane) = o4;
        __syncwarp();
    }
}

// ---------------------------------------------------------------------------
// Launch. __device__ symbols resolved via cudaGetSymbolAddress (round-8 fix).
// Dynamic smem for the double-buffered GEMM (cudaFuncSetAttribute is a host
// attribute query/set, not a stream op — graph-capture legal).
// ---------------------------------------------------------------------------
extern "C" void kernel_launch(void* const* d_in, const int* in_sizes, int n_in,
                              void* d_out, int out_size) {
    const float* x     = (const float*)d_in[0];   // (N, 128)
    const float* H     = (const float*)d_in[1];   // (N, E)
    const float* W     = (const float*)d_in[2];   // (128, 128)
    const float* bias  = (const float*)d_in[3];   // (128,)
    const float* gamma = (const float*)d_in[4];   // (128,)
    const float* beta  = (const float*)d_in[5];   // (128,)
    float* out = (float*)d_out;

    float *p_m1 = nullptr, *p_m2 = nullptr, *p_m4 = nullptr;
    cudaGetSymbolAddress((void**)&p_m1, g_m1);
    cudaGetSymbolAddress((void**)&p_m2, g_m2);
    cudaGetSymbolAddress((void**)&p_m4, g_m4);

    constexpr int SMEM_G1 = 2 * (32 * 136 + 32 * 136) * 4;   // 69632 B
    constexpr int SMEM_G2 = 2 * (128 * 36 + 32 * 136) * 4;   // 71680 B
    cudaFuncSetAttribute(k_gemm<true, true>,
                         cudaFuncAttributeMaxDynamicSharedMemorySize, SMEM_G1);
    cudaFuncSetAttribute(k_gemm<false, false>,
                         cudaFuncAttributeMaxDynamicSharedMemorySize, SMEM_G2);

    // 0. zero d_e + m2 (split-K accumulator)
    k_zero<<<(EE * DD + 255) / 256, 256>>>();
    // 1. degrees (single pass over H)
    k_deg<<<NN / 128, 256>>>(H);
    // 2. s, m1 = tf32(s.*x), de_inv
    k_prep<<<(NN * DD) / 256, 256>>>(x);
    // 3. GEMM1: m2 += H^T @ m1   (M=E, K=N, split-K=4, atomic)
    k_gemm<true, true><<<dim3(EE / 128, 4), 256, SMEM_G1>>>(H, p_m1, p_m2, NN / 4);
    // 4. m3 = tf32(de_inv .* m2) (in place)
    k_scale<<<(EE * DD) / 256, 256>>>();
    // 5. GEMM2: m4 = H @ m3      (M=N, K=E)
    k_gemm<false, false><<<dim3(NN / 128, 1), 256, SMEM_G2>>>(H, p_m2, p_m4, EE);
    // 6. linear + relu + layernorm
    k_final<<<256, 256>>>(W, bias, gamma, beta, out);
}

// round 12
// speedup vs baseline: 1.2957x; 1.1056x over previous
#include <cuda_runtime.h>
#include <cstdint>
#include <math.h>

// Problem constants
#define NN 32768
#define EE 8192
#define DD 128

// Scratch (static __device__ arrays — allocation-free per harness rules)
__device__ float g_dv[NN];        // node degrees
__device__ float g_de[EE];        // hyperedge degrees
__device__ float g_s[NN];         // dv_inv_sqrt
__device__ float g_dei[EE];       // de_inv
__device__ float g_m1[NN * DD];   // m1T [128 d][32768 n] = tf32(s .* x)^T
__device__ float g_m2[EE * DD];   // m2T [128 d][8192 e]  = m1T @ H ; then tf32(* dei)
__device__ float g_m4[NN * DD];   // m4  [32768 v][128 d] = H @ m3T^T

// ---------------------------------------------------------------------------
// helpers
// ---------------------------------------------------------------------------
__device__ __forceinline__ unsigned f2tf(float f) {
    unsigned u;
    asm("cvt.rna.tf32.f32 %0, %1;" : "=r"(u) : "f"(f));
    return u;
}

__device__ __forceinline__ void mma8(float* c, const unsigned* a, const unsigned* b) {
    asm volatile(
        "mma.sync.aligned.m16n8k8.row.col.f32.tf32.tf32.f32 "
        "{%0,%1,%2,%3}, {%4,%5,%6,%7}, {%8,%9}, {%0,%1,%2,%3};\n"
        : "+f"(c[0]), "+f"(c[1]), "+f"(c[2]), "+f"(c[3])
        : "r"(a[0]), "r"(a[1]), "r"(a[2]), "r"(a[3]), "r"(b[0]), "r"(b[1]));
}

__device__ __forceinline__ void cp16(unsigned dst, const void* src) {
    asm volatile("cp.async.cg.shared.global [%0], [%1], 16;\n" :: "r"(dst), "l"(src));
}
__device__ __forceinline__ void cp_commit() { asm volatile("cp.async.commit_group;\n"); }
template <int N>
__device__ __forceinline__ void cp_wait() {
    asm volatile("cp.async.wait_group %0;\n" :: "n"(N) : "memory");
}

// ldmatrix x4: four 8x8 b16 tiles == four 8x4 b32 tiles (tf32 fragments)
__device__ __forceinline__ void ldsm4(unsigned& r0, unsigned& r1, unsigned& r2,
                                      unsigned& r3, unsigned addr) {
    asm volatile("ldmatrix.sync.aligned.m8n8.x4.shared.b16 {%0,%1,%2,%3}, [%4];"
                 : "=r"(r0), "=r"(r1), "=r"(r2), "=r"(r3) : "r"(addr));
}

// ---------------------------------------------------------------------------
// Kernel 0: zero d_e and m2T (m2T receives split-K atomic adds)
// ---------------------------------------------------------------------------
__global__ void k_zero() {
    int i = blockIdx.x * 256 + threadIdx.x;
    if (i < EE * DD) g_m2[i] = 0.0f;
    if (i < EE) g_de[i] = 0.0f;
}

// ---------------------------------------------------------------------------
// Kernel 1: one pass over H -> row sums (d_v) and col sums (d_e)
// ---------------------------------------------------------------------------
__global__ __launch_bounds__(256) void k_deg(const float* __restrict__ H) {
    __shared__ float rowacc[128];
    const int t = threadIdx.x;
    if (t < 128) rowacc[t] = 0.0f;
    __syncthreads();

    const int r0 = blockIdx.x * 128;
    float col[32];
#pragma unroll
    for (int j = 0; j < 32; j++) col[j] = 0.0f;

    const float4* H4 = reinterpret_cast<const float4*>(H);
    for (int r = 0; r < 128; r++) {
        const float4* row = H4 + (size_t)(r0 + r) * (EE / 4);
        float rs = 0.0f;
#pragma unroll
        for (int j = 0; j < 8; j++) {
            float4 v = row[t * 8 + j];
            col[j * 4 + 0] += v.x;
            col[j * 4 + 1] += v.y;
            col[j * 4 + 2] += v.z;
            col[j * 4 + 3] += v.w;
            rs += (v.x + v.y) + (v.z + v.w);
        }
#pragma unroll
        for (int o = 16; o > 0; o >>= 1) rs += __shfl_xor_sync(0xffffffffu, rs, o);
        if ((t & 31) == 0) atomicAdd(&rowacc[r], rs);
    }
    __syncthreads();
    if (t < 128) g_dv[r0 + t] = rowacc[t];

#pragma unroll
    for (int j = 0; j < 32; j++) atomicAdd(&g_de[t * 32 + j], col[j]);
}

// ---------------------------------------------------------------------------
// Kernel 2a: s = 1/(sqrt(dv)+eps); dei = 1/(de+eps)
// ---------------------------------------------------------------------------
__global__ void k_inv() {
    int i = blockIdx.x * 256 + threadIdx.x;
    if (i < NN) g_s[i] = 1.0f / (sqrtf(g_dv[i]) + 1e-8f);
    if (i < EE) g_dei[i] = 1.0f / (g_de[i] + 1e-8f);
}

// ---------------------------------------------------------------------------
// Kernel 2b: m1T[d, n] = tf32(s[n] * x[n, d]) — tiled 32x32 transpose
// ---------------------------------------------------------------------------
__global__ __launch_bounds__(256) void k_m1t(const float* __restrict__ x) {
    __shared__ float tile[32][33];
    const int tx = threadIdx.x & 31, ty = threadIdx.x >> 5;
    const int n0 = blockIdx.x * 32, d0 = blockIdx.y * 32;
#pragma unroll
    for (int j = 0; j < 4; j++) {
        int n = n0 + ty + j * 8;
        tile[ty + j * 8][tx] = g_s[n] * x[(size_t)n * DD + d0 + tx];
    }
    __syncthreads();
#pragma unroll
    for (int j = 0; j < 4; j++) {
        int d = d0 + ty + j * 8;
        g_m1[(size_t)d * NN + n0 + tx] = __uint_as_float(f2tf(tile[tx][ty + j * 8]));
    }
}

// ---------------------------------------------------------------------------
// Kernel 4: m3T = tf32(m2T * dei[e]) (in place; e = fast dim of m2T)
// ---------------------------------------------------------------------------
__global__ void k_scale() {
    int i = blockIdx.x * 256 + threadIdx.x;
    if (i < EE * DD) g_m2[i] = __uint_as_float(f2tf(g_m2[i] * g_dei[i & (EE - 1)]));
}

// ---------------------------------------------------------------------------
// GEMM1: m2T[d, e-tile] += sum_n m1T[d, n] * H[n, e]
//   M=128 (d, whole extent per CTA), N tile 128 (e), K = n (split 4).
//   A = m1T smem [m=d][36]  (LDSM fragments)
//   B = H   smem [k=n][136] (scalar .col fragments, as validated in R9/R10)
//   3-stage cp.async pipeline, wait_group 1. 8 warps (4m x 2n), warp 32x64.
// ---------------------------------------------------------------------------
__global__ __launch_bounds__(256, 2) void k_gemm1(const float* __restrict__ H,
                                                  const float* __restrict__ m1t,
                                                  float* __restrict__ m2t) {
    extern __shared__ __align__(16) float sm[];
    constexpr int ASZ = 128 * 36;   // 4608 floats
    constexpr int BSZ = 32 * 136;   // 4352 floats
    constexpr int STG = ASZ + BSZ;  // 8960 floats / stage (35840 B)

    const int t = threadIdx.x;
    const int lane = t & 31;
    const int w = t >> 5;
    const int wm = w & 3;
    const int wn = w >> 2;
    const int e0 = blockIdx.x * 128;
    const int kb = blockIdx.y * (NN / 4);
    const unsigned sbase = (unsigned)__cvta_generic_to_shared(sm);

    float acc[2][8][4];
#pragma unroll
    for (int mt = 0; mt < 2; mt++)
#pragma unroll
        for (int nt = 0; nt < 8; nt++)
#pragma unroll
            for (int i = 0; i < 4; i++) acc[mt][nt][i] = 0.0f;

    auto issue = [&](int kt) {
        const unsigned ab = sbase + (unsigned)((kt % 3) * STG) * 4u;
        const unsigned bb = ab + ASZ * 4u;
        const int n0 = kb + kt * 32;
#pragma unroll
        for (int i = 0; i < 4; i++) {            // A: 128 d-rows x 8 chunks
            int c = t + i * 256;
            int r = c >> 3, q = c & 7;
            cp16(ab + (unsigned)(r * 36 + q * 4) * 4u, m1t + (size_t)r * NN + n0 + q * 4);
        }
#pragma unroll
        for (int i = 0; i < 4; i++) {            // B: 32 n-rows x 32 chunks
            int c = t + i * 256;
            int r = c >> 5, q = c & 31;
            cp16(bb + (unsigned)(r * 136 + q * 4) * 4u,
                 H + (size_t)(n0 + r) * EE + e0 + q * 4);
        }
        cp_commit();
    };

    issue(0);
    issue(1);

    const int iters = (NN / 4) / 32;             // 256
    const int gid = lane >> 2, tig = lane & 3;
    // LDSM lane->address components (constant over iters)
    const int lrow = lane & 7;
    const int lmh = (lane >> 3) & 1;             // +8 m-rows for matrices 1,3
    const int lkh = (lane >> 4) << 2;            // +4 k-cols for matrices 2,3

    for (int kt = 0; kt < iters; kt++) {
        cp_wait<1>();
        __syncthreads();                          // all warps done with stage kt-1
        if (kt + 2 < iters) issue(kt + 2);        // reuses buffer (kt-1)%3: safe

        const unsigned ab = sbase + (unsigned)((kt % 3) * STG) * 4u;
        const float* bs = sm + (kt % 3) * STG + ASZ;
#pragma unroll
        for (int ks = 0; ks < 4; ks++) {
            const int kr = ks * 8;
            unsigned af[2][4];
#pragma unroll
            for (int mt = 0; mt < 2; mt++) {
                int m = wm * 32 + mt * 16 + lmh * 8 + lrow;
                ldsm4(af[mt][0], af[mt][1], af[mt][2], af[mt][3],
                      ab + (unsigned)(m * 36 + kr + lkh) * 4u);
            }
            unsigned bf[8][2];
#pragma unroll
            for (int nt = 0; nt < 8; nt++) {
                int bn = wn * 64 + nt * 8 + gid;
                bf[nt][0] = __float_as_uint(bs[(kr + tig) * 136 + bn]);
                bf[nt][1] = __float_as_uint(bs[(kr + tig + 4) * 136 + bn]);
            }
#pragma unroll
            for (int mt = 0; mt < 2; mt++)
#pragma unroll
                for (int nt = 0; nt < 8; nt++) mma8(acc[mt][nt], af[mt], bf[nt]);
        }
    }

    // Epilogue: D[m=d][n=e]; c0:(g,2t) c1:(g,2t+1) c2:(g+8,2t) c3:(g+8,2t+1)
#pragma unroll
    for (int mt = 0; mt < 2; mt++) {
#pragma unroll
        for (int nt = 0; nt < 8; nt++) {
            int d = wm * 32 + mt * 16 + gid;
            int e = e0 + wn * 64 + nt * 8 + 2 * tig;
            float* p = m2t + (size_t)d * EE + e;
            atomicAdd(p, acc[mt][nt][0]);
            atomicAdd(p + 1, acc[mt][nt][1]);
            atomicAdd(p + 8 * EE, acc[mt][nt][2]);
            atomicAdd(p + 8 * EE + 1, acc[mt][nt][3]);
        }
    }
}

// ---------------------------------------------------------------------------
// GEMM2: m4[v-tile, d] = sum_e H[v, e] * m3T[d, e]
//   A = H   smem [m=v][36] (LDSM), B = m3T smem [n=d][36] (LDSM).
//   Block tile 128x128, K = e. 3-stage cp.async pipeline. grid = N/128.
// ---------------------------------------------------------------------------
__global__ __launch_bounds__(256, 2) void k_gemm2(const float* __restrict__ H,
                                                  const float* __restrict__ m3t,
                                                  float* __restrict__ m4) {
    extern __shared__ __align__(16) float sm[];
    constexpr int ASZ = 128 * 36;
    constexpr int BSZ = 128 * 36;
    constexpr int STG = ASZ + BSZ;               // 9216 floats / stage (36864 B)

    const int t = threadIdx.x;
    const int lane = t & 31;
    const int w = t >> 5;
    const int wm = w & 3;
    const int wn = w >> 2;
    const int v0 = blockIdx.x * 128;
    const unsigned sbase = (unsigned)__cvta_generic_to_shared(sm);

    float acc[2][8][4];
#pragma unroll
    for (int mt = 0; mt < 2; mt++)
#pragma unroll
        for (int nt = 0; nt < 8; nt++)
#pragma unroll
            for (int i = 0; i < 4; i++) acc[mt][nt][i] = 0.0f;

    auto issue = [&](int kt) {
        const unsigned ab = sbase + (unsigned)((kt % 3) * STG) * 4u;
        const unsigned bb = ab + ASZ * 4u;
        const int ke = kt * 32;
#pragma unroll
        for (int i = 0; i < 4; i++) {            // A: H 128 v-rows x 8 chunks
            int c = t + i * 256;
            int r = c >> 3, q = c & 7;
            cp16(ab + (unsigned)(r * 36 + q * 4) * 4u,
                 H + (size_t)(v0 + r) * EE + ke + q * 4);
        }
#pragma unroll
        for (int i = 0; i < 4; i++) {            // B: m3T 128 d-rows x 8 chunks
            int c = t + i * 256;
            int r = c >> 3, q = c & 7;
            cp16(bb + (unsigned)(r * 36 + q * 4) * 4u,
                 m3t + (size_t)r * EE + ke + q * 4);
        }
        cp_commit();
    };

    issue(0);
    issue(1);

    const int iters = EE / 32;                    // 256
    const int gid = lane >> 2, tig = lane & 3;
    const int lrow = lane & 7;
    const int lmh = (lane >> 3) & 1;
    const int lkh = (lane >> 4) << 2;
    // B-LDSM lane map: matrices (b0[2p], b1[2p], b0[2p+1], b1[2p+1])
    const int bnh = (lane >> 4) << 3;             // +8 n-rows for matrices 2,3
    const int bkh = ((lane >> 3) & 1) << 2;       // +4 k-cols for matrices 1,3

    for (int kt = 0; kt < iters; kt++) {
        cp_wait<1>();
        __syncthreads();
        if (kt + 2 < iters) issue(kt + 2);

        const unsigned ab = sbase + (unsigned)((kt % 3) * STG) * 4u;
        const unsigned bb = ab + ASZ * 4u;
#pragma unroll
        for (int ks = 0; ks < 4; ks++) {
            const int kr = ks * 8;
            unsigned af[2][4];
#pragma unroll
            for (int mt = 0; mt < 2; mt++) {
                int m = wm * 32 + mt * 16 + lmh * 8 + lrow;
                ldsm4(af[mt][0], af[mt][1], af[mt][2], af[mt][3],
                      ab + (unsigned)(m * 36 + kr + lkh) * 4u);
            }
            unsigned bf[8][2];
#pragma unroll
            for (int p = 0; p < 4; p++) {
                int n = wn * 64 + p * 16 + bnh + lrow;
                unsigned r0, r1, r2, r3;
                ldsm4(r0, r1, r2, r3, bb + (unsigned)(n * 36 + kr + bkh) * 4u);
                bf[2 * p][0] = r0;
                bf[2 * p][1] = r1;
                bf[2 * p + 1][0] = r2;
                bf[2 * p + 1][1] = r3;
            }
#pragma unroll
            for (int mt = 0; mt < 2; mt++)
#pragma unroll
                for (int nt = 0; nt < 8; nt++) mma8(acc[mt][nt], af[mt], bf[nt]);
        }
    }

    // Epilogue: D[m=v][n=d] plain store
#pragma unroll
    for (int mt = 0; mt < 2; mt++) {
#pragma unroll
        for (int nt = 0; nt < 8; nt++) {
            int m = v0 + wm * 32 + mt * 16 + gid;
            int n = wn * 64 + nt * 8 + 2 * tig;
            float* p = m4 + (size_t)m * DD + n;
            p[0] = acc[mt][nt][0];
            p[1] = acc[mt][nt][1];
            p[8 * DD] = acc[mt][nt][2];
            p[8 * DD + 1] = acc[mt][nt][3];
        }
    }
}

// ---------------------------------------------------------------------------
// Kernel 6: per row n:  v = s[n]*m4[n,:];  h = W@v + b;  relu;  layernorm.
// ---------------------------------------------------------------------------
__global__ __launch_bounds__(256) void k_final(const float* __restrict__ W,
                                               const float* __restrict__ bias,
                                               const float* __restrict__ gamma,
                                               const float* __restrict__ beta,
                                               float* __restrict__ out) {
    __shared__ float vbuf[8][132];
    const int t = threadIdx.x;
    const int lane = t & 31;
    const int w = t >> 5;

    const float4 bb = *reinterpret_cast<const float4*>(bias + 4 * lane);
    const float4 gg = *reinterpret_cast<const float4*>(gamma + 4 * lane);
    const float4 eb = *reinterpret_cast<const float4*>(beta + 4 * lane);
    const float4* W4 = reinterpret_cast<const float4*>(W);

    for (int n = blockIdx.x * 8 + w; n < NN; n += gridDim.x * 8) {
        const float s = g_s[n];
        float4 mv = *reinterpret_cast<const float4*>(g_m4 + (size_t)n * DD + 4 * lane);
        vbuf[w][4 * lane + 0] = s * mv.x;
        vbuf[w][4 * lane + 1] = s * mv.y;
        vbuf[w][4 * lane + 2] = s * mv.z;
        vbuf[w][4 * lane + 3] = s * mv.w;
        __syncwarp();

        float h0 = bb.x, h1 = bb.y, h2 = bb.z, h3 = bb.w;
#pragma unroll 8
        for (int dq = 0; dq < 32; dq++) {
            float4 v4 = *reinterpret_cast<float4*>(&vbuf[w][dq * 4]);
            float4 w0 = W4[(4 * lane + 0) * 32 + dq];
            float4 w1 = W4[(4 * lane + 1) * 32 + dq];
            float4 w2 = W4[(4 * lane + 2) * 32 + dq];
            float4 w3 = W4[(4 * lane + 3) * 32 + dq];
            h0 += w0.x * v4.x + w0.y * v4.y + w0.z * v4.z + w0.w * v4.w;
            h1 += w1.x * v4.x + w1.y * v4.y + w1.z * v4.z + w1.w * v4.w;
            h2 += w2.x * v4.x + w2.y * v4.y + w2.z * v4.z + w2.w * v4.w;
            h3 += w3.x * v4.x + w3.y * v4.y + w3.z * v4.z + w3.w * v4.w;
        }
        h0 = fmaxf(h0, 0.0f);
        h1 = fmaxf(h1, 0.0f);
        h2 = fmaxf(h2, 0.0f);
        h3 = fmaxf(h3, 0.0f);

        float sum = h0 + h1 + h2 + h3;
#pragma unroll
        for (int o = 16; o > 0; o >>= 1) sum += __shfl_xor_sync(0xffffffffu, sum, o);
        const float mu = sum * (1.0f / 128.0f);
        const float d0 = h0 - mu, d1 = h1 - mu, d2 = h2 - mu, d3 = h3 - mu;
        float vs = d0 * d0 + d1 * d1 + d2 * d2 + d3 * d3;
#pragma unroll
        for (int o = 16; o > 0; o >>= 1) vs += __shfl_xor_sync(0xffffffffu, vs, o);
        const float inv = rsqrtf(vs * (1.0f / 128.0f) + 1e-5f);

        float4 o4;
        o4.x = gg.x * d0 * inv + eb.x;
        o4.y = gg.y * d1 * inv + eb.y;
        o4.z = gg.z * d2 * inv + eb.z;
        o4.w = gg.w * d3 * inv + eb.w;
        *reinterpret_cast<float4*>(out + (size_t)n * DD + 4 * lane) = o4;
        __syncwarp();
    }
}

// ---------------------------------------------------------------------------
// Launch
// ---------------------------------------------------------------------------
extern "C" void kernel_launch(void* const* d_in, const int* in_sizes, int n_in,
                              void* d_out, int out_size) {
    const float* x     = (const float*)d_in[0];   // (N, 128)
    const float* H     = (const float*)d_in[1];   // (N, E)
    const float* W     = (const float*)d_in[2];   // (128, 128)
    const float* bias  = (const float*)d_in[3];   // (128,)
    const float* gamma = (const float*)d_in[4];   // (128,)
    const float* beta  = (const float*)d_in[5];   // (128,)
    float* out = (float*)d_out;

    // Resolve true device addresses of scratch symbols (round-8 fix).
    float *p_m1 = nullptr, *p_m2 = nullptr, *p_m4 = nullptr;
    cudaGetSymbolAddress((void**)&p_m1, g_m1);
    cudaGetSymbolAddress((void**)&p_m2, g_m2);
    cudaGetSymbolAddress((void**)&p_m4, g_m4);

    constexpr int SMEM_G1 = 3 * (128 * 36 + 32 * 136) * 4;   // 107520 B
    constexpr int SMEM_G2 = 3 * (128 * 36 + 128 * 36) * 4;   // 110592 B
    cudaFuncSetAttribute(k_gemm1, cudaFuncAttributeMaxDynamicSharedMemorySize, SMEM_G1);
    cudaFuncSetAttribute(k_gemm2, cudaFuncAttributeMaxDynamicSharedMemorySize, SMEM_G2);

    // 0. zero d_e + m2T (split-K accumulator)
    k_zero<<<(EE * DD + 255) / 256, 256>>>();
    // 1. degrees (single pass over H)
    k_deg<<<NN / 128, 256>>>(H);
    // 2. s, dei;  m1T = tf32(s .* x)^T
    k_inv<<<NN / 256, 256>>>();
    k_m1t<<<dim3(NN / 32, DD / 32), 256>>>(x);
    // 3. GEMM1: m2T += m1T @ H   (split-K=4, atomic)
    k_gemm1<<<dim3(EE / 128, 4), 256, SMEM_G1>>>(H, p_m1, p_m2);
    // 4. m3T = tf32(m2T .* dei[e]) (in place)
    k_scale<<<(EE * DD) / 256, 256>>>();
    // 5. GEMM2: m4 = H @ m3T^T
    k_gemm2<<<NN / 128, 256, SMEM_G2>>>(H, p_m2, p_m4);
    // 6. linear + relu + layernorm
    k_final<<<256, 256>>>(W, bias, gamma, beta, out);
}